// round 1
// baseline (speedup 1.0000x reference)
#include <cuda_runtime.h>
#include <math.h>

#define HIDDEN   1024
#define BATCH    512
#define FEAT     1024
#define TSTEPS   100
#define TIME_TOT 103
#define FOURH    4096

// ---------------- scratch (static device globals; no allocs) ----------------
__device__ float g_xp[(size_t)TSTEPS * BATCH * FEAT];    // packed X: [T][B][F]   (210 MB)
__device__ float g_zx[(size_t)TSTEPS * BATCH * FOURH];   // X@W + b : [T][B][4H]  (839 MB)
__device__ float g_z [(size_t)BATCH * FOURH];            // per-step z            (8 MB)
__device__ float g_h [(size_t)BATCH * HIDDEN];
__device__ float g_c [(size_t)BATCH * HIDDEN];

// ---------------- init: zero h, c (must be re-done every call) --------------
__global__ void init_state() {
    int i = blockIdx.x * blockDim.x + threadIdx.x;
    if (i < BATCH * HIDDEN) { g_h[i] = 0.f; g_c[i] = 0.f; }
}

// ---------------- pack: x[b, t<100, f] -> g_xp[t, b, f] ---------------------
__global__ void pack_x(const float* __restrict__ x) {
    size_t p4 = (size_t)blockIdx.x * blockDim.x + threadIdx.x;
    const size_t total4 = (size_t)TSTEPS * BATCH * FEAT / 4;
    if (p4 >= total4) return;
    size_t p = p4 * 4;
    int k  = (int)(p & (FEAT - 1));
    int bt = (int)(p >> 10);           // FEAT = 1024
    int t  = bt / BATCH;
    int b  = bt % BATCH;
    float4 v = *(const float4*)(x + ((size_t)b * TIME_TOT + t) * FEAT + k);
    *(float4*)(g_xp + p) = v;
}

// ---------------- tiled SGEMM: C = A[M,K] @ B[K,N] + Add ---------------------
// MODE 0: Add is bias[N] (broadcast).  MODE 1: Add is full [M,N].
// BM=BN=128, BK=8, 256 threads, 8x8 microtile (split 4+4 with 64 offset).
template <int MODE>
__global__ void __launch_bounds__(256, 2)
sgemm128(const float* __restrict__ A, const float* __restrict__ B,
         const float* __restrict__ Add, float* __restrict__ C,
         int M, int N, int K)
{
    __shared__ float As[8][128];
    __shared__ float Bs[8][128];

    const int bx = blockIdx.x, by = blockIdx.y;
    const int tid = threadIdx.x;
    const int tx = tid & 15;     // 0..15
    const int ty = tid >> 4;     // 0..15

    float acc[8][8];
#pragma unroll
    for (int i = 0; i < 8; i++)
#pragma unroll
        for (int j = 0; j < 8; j++) acc[i][j] = 0.f;

    const int a_row = tid >> 1;          // 0..127
    const int a_col = (tid & 1) << 2;    // 0 or 4
    const int b_row = tid >> 5;          // 0..7
    const int b_col = (tid & 31) << 2;   // 0..124

    const float* Ap = A + (size_t)(by * 128 + a_row) * K + a_col;
    const float* Bp = B + (size_t)b_row * N + (size_t)bx * 128 + b_col;

    for (int k0 = 0; k0 < K; k0 += 8) {
        float4 av = *(const float4*)(Ap + k0);
        float4 bv = *(const float4*)(Bp + (size_t)k0 * N);
        As[a_col + 0][a_row] = av.x;
        As[a_col + 1][a_row] = av.y;
        As[a_col + 2][a_row] = av.z;
        As[a_col + 3][a_row] = av.w;
        *(float4*)&Bs[b_row][b_col] = bv;
        __syncthreads();

#pragma unroll
        for (int kk = 0; kk < 8; kk++) {
            float ra[8], rb[8];
            *(float4*)&ra[0] = *(const float4*)&As[kk][ty * 4];
            *(float4*)&ra[4] = *(const float4*)&As[kk][ty * 4 + 64];
            *(float4*)&rb[0] = *(const float4*)&Bs[kk][tx * 4];
            *(float4*)&rb[4] = *(const float4*)&Bs[kk][tx * 4 + 64];
#pragma unroll
            for (int i = 0; i < 8; i++)
#pragma unroll
                for (int j = 0; j < 8; j++)
                    acc[i][j] += ra[i] * rb[j];
        }
        __syncthreads();
    }

    // epilogue: rows = by*128 + ty*4 + ih*64 + r,  cols = bx*128 + tx*4 + jh*64 + c
#pragma unroll
    for (int ih = 0; ih < 2; ih++) {
#pragma unroll
        for (int r = 0; r < 4; r++) {
            int m = by * 128 + ty * 4 + ih * 64 + r;
#pragma unroll
            for (int jh = 0; jh < 2; jh++) {
                int n = bx * 128 + tx * 4 + jh * 64;
                float4 v;
                v.x = acc[ih * 4 + r][jh * 4 + 0];
                v.y = acc[ih * 4 + r][jh * 4 + 1];
                v.z = acc[ih * 4 + r][jh * 4 + 2];
                v.w = acc[ih * 4 + r][jh * 4 + 3];
                if (MODE == 0) {
                    float4 bb = *(const float4*)(Add + n);
                    v.x += bb.x; v.y += bb.y; v.z += bb.z; v.w += bb.w;
                } else {
                    float4 aa = *(const float4*)(Add + (size_t)m * N + n);
                    v.x += aa.x; v.y += aa.y; v.z += aa.z; v.w += aa.w;
                }
                *(float4*)(C + (size_t)m * N + n) = v;
            }
        }
    }
}

// ---------------- pointwise LSTM gates + state update ------------------------
__global__ void lstm_pointwise(float* __restrict__ out, int t) {
    int idx = blockIdx.x * blockDim.x + threadIdx.x;
    if (idx >= BATCH * HIDDEN) return;
    int b = idx >> 10;          // HIDDEN = 1024
    int j = idx & (HIDDEN - 1);
    const float* zrow = g_z + (size_t)b * FOURH;
    float zi = zrow[j];
    float zf = zrow[HIDDEN + j];
    float zg = zrow[2 * HIDDEN + j];
    float zo = zrow[3 * HIDDEN + j];

    float si = 1.f / (1.f + expf(-zi));
    float sf = 1.f / (1.f + expf(-zf));
    float so = 1.f / (1.f + expf(-zo));
    float tg = tanhf(zg);

    float cn = sf * g_c[idx] + si * tg;
    float hn = so * tanhf(cn);
    g_c[idx] = cn;
    g_h[idx] = hn;
    out[(size_t)b * TSTEPS * HIDDEN + (size_t)t * HIDDEN + j] = hn;
}

// ---------------- launch ------------------------------------------------------
extern "C" void kernel_launch(void* const* d_in, const int* in_sizes, int n_in,
                              void* d_out, int out_size)
{
    const float* x    = (const float*)d_in[0];  // [512, 103, 1024]
    const float* W    = (const float*)d_in[1];  // [1024, 4096]
    const float* R    = (const float*)d_in[2];  // [1024, 4096]
    const float* bias = (const float*)d_in[3];  // [4096]
    float* out = (float*)d_out;                 // [512, 100, 1024]

    // resolve device-global scratch addresses (host-side, no allocation)
    float *zx_base;
    cudaGetSymbolAddress((void**)&zx_base, g_zx);
    float *xp_base;
    cudaGetSymbolAddress((void**)&xp_base, g_xp);
    float *z_base;
    cudaGetSymbolAddress((void**)&z_base, g_z);
    float *h_base;
    cudaGetSymbolAddress((void**)&h_base, g_h);

    // 1. zero h, c
    init_state<<<(BATCH * HIDDEN + 255) / 256, 256>>>();

    // 2. pack X -> [T, B, F]
    {
        size_t total4 = (size_t)TSTEPS * BATCH * FEAT / 4;
        pack_x<<<(unsigned)((total4 + 255) / 256), 256>>>(x);
    }

    // 3. big GEMM: g_zx = g_xp @ W + bias   (M = 51200)
    {
        dim3 grid(FOURH / 128, (TSTEPS * BATCH) / 128);
        sgemm128<0><<<grid, 256>>>(xp_base, W, bias, zx_base,
                                   TSTEPS * BATCH, FOURH, FEAT);
    }

    // 4. time loop: z = h @ R + zx[t]; gates
    dim3 grid2(FOURH / 128, BATCH / 128);
    for (int t = 0; t < TSTEPS; t++) {
        const float* zx_t = zx_base + (size_t)t * BATCH * FOURH;
        sgemm128<1><<<grid2, 256>>>(h_base, R, zx_t, z_base,
                                    BATCH, FOURH, HIDDEN);
        lstm_pointwise<<<(BATCH * HIDDEN + 255) / 256, 256>>>(out, t);
    }
}

// round 3
// speedup vs baseline: 2.3395x; 2.3395x over previous
#include <cuda_runtime.h>
#include <cstdint>
#include <math.h>

#define HIDDEN   1024
#define BATCH    512
#define FEAT     1024
#define TSTEPS   100
#define TIME_TOT 103
#define FOURH    4096

#define BM 128
#define BN 128
#define BK 32
#define NTHREADS 256
#define ASTRIDE 36    // floats per A smem row (pad 4)
#define BSTRIDE 136   // floats per B smem row (pad 8)
#define A_BYTES (BM * ASTRIDE * 4)       // 18432
#define B_BYTES (BK * BSTRIDE * 4)       // 17408
#define STAGE_BYTES (A_BYTES + B_BYTES)  // 35840
#define NSTAGES 3
#define SMEM_TOTAL (NSTAGES * STAGE_BYTES)  // 107520

// ------------------------------ device state / scratch ----------------------
__device__ __align__(16) float g_h[BATCH * HIDDEN];
__device__ __align__(16) float g_c[BATCH * HIDDEN];
__device__ __align__(16) float g_zx[(size_t)TSTEPS * BATCH * FOURH];  // [t][b][4096]

// ------------------------------ helpers -------------------------------------
#define CP16(dst, src) \
    asm volatile("cp.async.cg.shared.global [%0], [%1], 16;" :: "r"(dst), "l"(src))
#define CP_COMMIT() asm volatile("cp.async.commit_group;" ::: "memory")
#define CP_WAIT1()  asm volatile("cp.async.wait_group 1;" ::: "memory")

__device__ __forceinline__ void mma_tf32(float c[4],
    uint32_t a0, uint32_t a1, uint32_t a2, uint32_t a3, uint32_t b0, uint32_t b1)
{
    asm volatile(
        "mma.sync.aligned.m16n8k8.row.col.f32.tf32.tf32.f32 "
        "{%0,%1,%2,%3}, {%4,%5,%6,%7}, {%8,%9}, {%0,%1,%2,%3};"
        : "+f"(c[0]), "+f"(c[1]), "+f"(c[2]), "+f"(c[3])
        : "r"(a0), "r"(a1), "r"(a2), "r"(a3), "r"(b0), "r"(b1));
}

// Compute one 128x128x32 tile. Warp layout: wm in {0,1} (64 rows), wn in {0..3}.
// Warp n-tiles are strided across the 4 gate blocks: cols g*32 + wn*8.
__device__ __forceinline__ void compute_tile(
    const float* __restrict__ As, const float* __restrict__ Bs,
    float acc[4][4][4], int lane, int wm, int wn)
{
    const int grp = lane >> 2, tig = lane & 3;
#pragma unroll
    for (int k8 = 0; k8 < 4; k8++) {
        const int kb = k8 * 8;
        uint32_t af[4][4];
#pragma unroll
        for (int mi = 0; mi < 4; mi++) {
            const float* ap = As + (wm * 64 + mi * 16 + grp) * ASTRIDE + kb + tig;
            af[mi][0] = __float_as_uint(ap[0]);
            af[mi][1] = __float_as_uint(ap[8 * ASTRIDE]);
            af[mi][2] = __float_as_uint(ap[4]);
            af[mi][3] = __float_as_uint(ap[8 * ASTRIDE + 4]);
        }
        uint32_t bf[4][2];
#pragma unroll
        for (int g = 0; g < 4; g++) {
            const float* bp = Bs + (kb + tig) * BSTRIDE + g * 32 + wn * 8 + grp;
            bf[g][0] = __float_as_uint(bp[0]);
            bf[g][1] = __float_as_uint(bp[4 * BSTRIDE]);
        }
#pragma unroll
        for (int mi = 0; mi < 4; mi++)
#pragma unroll
            for (int g = 0; g < 4; g++)
                mma_tf32(acc[mi][g], af[mi][0], af[mi][1], af[mi][2], af[mi][3],
                         bf[g][0], bf[g][1]);
    }
}

// ------------------------------ init ----------------------------------------
__global__ void init_state() {
    int i = blockIdx.x * blockDim.x + threadIdx.x;
    if (i < BATCH * HIDDEN) { g_h[i] = 0.f; g_c[i] = 0.f; }
}

// ------------------------------ big GEMM: zx = x @ W + bias ------------------
// grid (32, 400). m = t*512 + b; A row = x[b][t][:]. B = W plain columns.
__global__ void __launch_bounds__(NTHREADS, 1)
gemm_xw(const float* __restrict__ x, const float* __restrict__ W,
        const float* __restrict__ bias)
{
    extern __shared__ float smem[];
    const int tid = threadIdx.x, lane = tid & 31, wid = tid >> 5;
    const int wm = wid >> 2, wn = wid & 3;
    const int n0 = blockIdx.x * BN;
    const int m0 = blockIdx.y * BM;

    // per-thread load geometry
    const int arow = tid >> 1;                 // A: one gmem row per thread
    const int m = m0 + arow;
    const int tt = m >> 9, bb = m & 511;
    const float* ag = x + ((size_t)bb * TIME_TOT + tt) * FEAT + (tid & 1) * 16;
    const float* bg = W + (size_t)(tid >> 3) * FOURH + n0 + (tid & 7) * 16;

    const uint32_t sbase = (uint32_t)__cvta_generic_to_shared(smem);
    const uint32_t aoff = arow * (ASTRIDE * 4) + (tid & 1) * 64;
    const uint32_t boff = (tid >> 3) * (BSTRIDE * 4) + (tid & 7) * 64;

    float acc[4][4][4];
#pragma unroll
    for (int a = 0; a < 4; a++)
#pragma unroll
        for (int b = 0; b < 4; b++)
#pragma unroll
            for (int c = 0; c < 4; c++) acc[a][b][c] = 0.f;

    const int NK = FEAT / BK;  // 32
#pragma unroll
    for (int s = 0; s < 2; s++) {
        uint32_t sa = sbase + s * STAGE_BYTES + aoff;
        uint32_t sb = sbase + s * STAGE_BYTES + A_BYTES + boff;
        const float* agp = ag + s * BK;
        const float* bgp = bg + (size_t)s * BK * FOURH;
#pragma unroll
        for (int i = 0; i < 4; i++) { CP16(sa + i * 16, agp + i * 4); CP16(sb + i * 16, bgp + i * 4); }
        CP_COMMIT();
    }

    for (int kt = 0; kt < NK; kt++) {
        CP_WAIT1();
        __syncthreads();
        if (kt + 2 < NK) {
            int s = (kt + 2) % NSTAGES;
            uint32_t sa = sbase + s * STAGE_BYTES + aoff;
            uint32_t sb = sbase + s * STAGE_BYTES + A_BYTES + boff;
            const float* agp = ag + (kt + 2) * BK;
            const float* bgp = bg + (size_t)(kt + 2) * BK * FOURH;
#pragma unroll
            for (int i = 0; i < 4; i++) { CP16(sa + i * 16, agp + i * 4); CP16(sb + i * 16, bgp + i * 4); }
        }
        CP_COMMIT();
        const float* As = smem + (kt % NSTAGES) * (STAGE_BYTES / 4);
        const float* Bs = As + (A_BYTES / 4);
        compute_tile(As, Bs, acc, lane, wm, wn);
    }

    // epilogue: zx[m][col] = acc + bias[col]
    const int grp = lane >> 2, tig = lane & 3;
#pragma unroll
    for (int g = 0; g < 4; g++) {
        const int col = n0 + g * 32 + wn * 8 + 2 * tig;
        const float2 bv = *(const float2*)(bias + col);
#pragma unroll
        for (int mi = 0; mi < 4; mi++) {
            const int r0 = m0 + wm * 64 + mi * 16 + grp;
            float2 v0 = {acc[mi][g][0] + bv.x, acc[mi][g][1] + bv.y};
            float2 v1 = {acc[mi][g][2] + bv.x, acc[mi][g][3] + bv.y};
            *(float2*)(g_zx + (size_t)r0 * FOURH + col) = v0;
            *(float2*)(g_zx + (size_t)(r0 + 8) * FOURH + col) = v1;
        }
    }
}

// ------------------------------ recurrent step: z = h@R + zx[t]; gates -------
// grid (32, 4): bx -> hidden strip j0 = bx*32 (covers cols g*1024 + j0..j0+31
// for all 4 gates), by -> batch m0 = by*128.
__global__ void __launch_bounds__(NTHREADS, 1)
lstm_step(const float* __restrict__ R, float* __restrict__ out, int t)
{
    extern __shared__ float smem[];
    const int tid = threadIdx.x, lane = tid & 31, wid = tid >> 5;
    const int wm = wid >> 2, wn = wid & 3;
    const int j0 = blockIdx.x * 32;
    const int m0 = blockIdx.y * BM;

    const int arow = tid >> 1;
    const float* ag = g_h + (size_t)(m0 + arow) * HIDDEN + (tid & 1) * 16;
    const int gate = (tid & 7) >> 1;
    const float* bg = R + (size_t)(tid >> 3) * FOURH + gate * 1024 + j0 + (tid & 1) * 16;

    const uint32_t sbase = (uint32_t)__cvta_generic_to_shared(smem);
    const uint32_t aoff = arow * (ASTRIDE * 4) + (tid & 1) * 64;
    const uint32_t boff = (tid >> 3) * (BSTRIDE * 4) + (tid & 7) * 64;

    float acc[4][4][4];
#pragma unroll
    for (int a = 0; a < 4; a++)
#pragma unroll
        for (int b = 0; b < 4; b++)
#pragma unroll
            for (int c = 0; c < 4; c++) acc[a][b][c] = 0.f;

    const int NK = HIDDEN / BK;  // 32
#pragma unroll
    for (int s = 0; s < 2; s++) {
        uint32_t sa = sbase + s * STAGE_BYTES + aoff;
        uint32_t sb = sbase + s * STAGE_BYTES + A_BYTES + boff;
        const float* agp = ag + s * BK;
        const float* bgp = bg + (size_t)s * BK * FOURH;
#pragma unroll
        for (int i = 0; i < 4; i++) { CP16(sa + i * 16, agp + i * 4); CP16(sb + i * 16, bgp + i * 4); }
        CP_COMMIT();
    }

    for (int kt = 0; kt < NK; kt++) {
        CP_WAIT1();
        __syncthreads();
        if (kt + 2 < NK) {
            int s = (kt + 2) % NSTAGES;
            uint32_t sa = sbase + s * STAGE_BYTES + aoff;
            uint32_t sb = sbase + s * STAGE_BYTES + A_BYTES + boff;
            const float* agp = ag + (kt + 2) * BK;
            const float* bgp = bg + (size_t)(kt + 2) * BK * FOURH;
#pragma unroll
            for (int i = 0; i < 4; i++) { CP16(sa + i * 16, agp + i * 4); CP16(sb + i * 16, bgp + i * 4); }
        }
        CP_COMMIT();
        const float* As = smem + (kt % NSTAGES) * (STAGE_BYTES / 4);
        const float* Bs = As + (A_BYTES / 4);
        compute_tile(As, Bs, acc, lane, wm, wn);
    }

    // fused LSTM epilogue: thread owns all 4 gates for each (row, j) pair
    const int grp = lane >> 2, tig = lane & 3;
    const int jj = wn * 8 + 2 * tig;
    const int j = j0 + jj;
#pragma unroll
    for (int mi = 0; mi < 4; mi++) {
#pragma unroll
        for (int half = 0; half < 2; half++) {
            const int row = m0 + wm * 64 + mi * 16 + half * 8 + grp;
            const float* zrow = g_zx + ((size_t)t * BATCH + row) * FOURH + j0 + jj;
            const float2 xi = *(const float2*)(zrow);
            const float2 xf = *(const float2*)(zrow + 1024);
            const float2 xg = *(const float2*)(zrow + 2048);
            const float2 xo = *(const float2*)(zrow + 3072);
            const float2 cv = *(const float2*)(g_c + (size_t)row * HIDDEN + j);

            float zi0 = acc[mi][0][half * 2 + 0] + xi.x;
            float zf0 = acc[mi][1][half * 2 + 0] + xf.x;
            float zg0 = acc[mi][2][half * 2 + 0] + xg.x;
            float zo0 = acc[mi][3][half * 2 + 0] + xo.x;
            float zi1 = acc[mi][0][half * 2 + 1] + xi.y;
            float zf1 = acc[mi][1][half * 2 + 1] + xf.y;
            float zg1 = acc[mi][2][half * 2 + 1] + xg.y;
            float zo1 = acc[mi][3][half * 2 + 1] + xo.y;

            float si0 = 1.f / (1.f + expf(-zi0)), si1 = 1.f / (1.f + expf(-zi1));
            float sf0 = 1.f / (1.f + expf(-zf0)), sf1 = 1.f / (1.f + expf(-zf1));
            float so0 = 1.f / (1.f + expf(-zo0)), so1 = 1.f / (1.f + expf(-zo1));
            float tg0 = tanhf(zg0), tg1 = tanhf(zg1);

            float cn0 = sf0 * cv.x + si0 * tg0;
            float cn1 = sf1 * cv.y + si1 * tg1;
            float hn0 = so0 * tanhf(cn0);
            float hn1 = so1 * tanhf(cn1);

            float2 cno = {cn0, cn1}, hno = {hn0, hn1};
            *(float2*)(g_c + (size_t)row * HIDDEN + j) = cno;
            *(float2*)(g_h + (size_t)row * HIDDEN + j) = hno;
            *(float2*)(out + (size_t)row * (TSTEPS * HIDDEN) + (size_t)t * HIDDEN + j) = hno;
        }
    }
}

// ------------------------------ launch ---------------------------------------
extern "C" void kernel_launch(void* const* d_in, const int* in_sizes, int n_in,
                              void* d_out, int out_size)
{
    const float* x    = (const float*)d_in[0];  // [512, 103, 1024]
    const float* W    = (const float*)d_in[1];  // [1024, 4096]
    const float* R    = (const float*)d_in[2];  // [1024, 4096]
    const float* bias = (const float*)d_in[3];  // [4096]
    float* out = (float*)d_out;                 // [512, 100, 1024]

    cudaFuncSetAttribute(gemm_xw,  cudaFuncAttributeMaxDynamicSharedMemorySize, SMEM_TOTAL);
    cudaFuncSetAttribute(lstm_step, cudaFuncAttributeMaxDynamicSharedMemorySize, SMEM_TOTAL);

    init_state<<<(BATCH * HIDDEN + 255) / 256, 256>>>();

    dim3 gridBig(FOURH / BN, (TSTEPS * BATCH) / BM);   // (32, 400)
    gemm_xw<<<gridBig, NTHREADS, SMEM_TOTAL>>>(x, W, bias);

    dim3 gridStep(HIDDEN / 32, BATCH / BM);            // (32, 4)
    for (int t = 0; t < TSTEPS; t++)
        lstm_step<<<gridStep, NTHREADS, SMEM_TOTAL>>>(R, out, t);
}

// round 4
// speedup vs baseline: 3.1551x; 1.3486x over previous
#include <cuda_runtime.h>
#include <cstdint>
#include <math.h>

#define HIDDEN   1024
#define BATCH    512
#define FEAT     1024
#define TSTEPS   100
#define TIME_TOT 103
#define FOURH    4096
#define MTOT     (TSTEPS * BATCH)   // 51200

#define SMEM_SZ  131072   // 4 stages x (16KB A + 16KB B)

// ------------------------------ scratch (device globals, no allocs) ----------
__device__ __align__(16) float g_Wp[32 * 32 * 4096];            // permuted W (16MB)
__device__ __align__(16) float g_Rp[32 * 32 * 4096];            // permuted R (16MB)
__device__ __align__(16) float g_xp[(size_t)MTOT * 1024];       // permuted x (210MB)
__device__ __align__(16) float g_zxp[(size_t)MTOT * 4096];      // x@W+b, gate-packed (839MB)
__device__ __align__(16) float g_hp[2][BATCH * HIDDEN];         // permuted h, ping-pong
__device__ __align__(16) float g_c [BATCH * HIDDEN];

// ------------------------------ asm helpers ----------------------------------
#define CP16(dst, src) \
    asm volatile("cp.async.cg.shared.global [%0], [%1], 16;" :: "r"(dst), "l"(src))
#define CP_COMMIT() asm volatile("cp.async.commit_group;" ::: "memory")
#define CP_WAIT2()  asm volatile("cp.async.wait_group 2;" ::: "memory")

__device__ __forceinline__ float4 lds128(uint32_t a) {
    float4 v;
    asm volatile("ld.shared.v4.f32 {%0,%1,%2,%3}, [%4];"
                 : "=f"(v.x), "=f"(v.y), "=f"(v.z), "=f"(v.w) : "r"(a));
    return v;
}
__device__ __forceinline__ float2 lds64(uint32_t a) {
    float2 v;
    asm volatile("ld.shared.v2.f32 {%0,%1}, [%2];" : "=f"(v.x), "=f"(v.y) : "r"(a));
    return v;
}
__device__ __forceinline__ void mma_tf32(float c[4], float4 a, float2 b) {
    asm volatile(
        "mma.sync.aligned.m16n8k8.row.col.f32.tf32.tf32.f32 "
        "{%0,%1,%2,%3}, {%4,%5,%6,%7}, {%8,%9}, {%0,%1,%2,%3};"
        : "+f"(c[0]), "+f"(c[1]), "+f"(c[2]), "+f"(c[3])
        : "r"(__float_as_uint(a.x)), "r"(__float_as_uint(a.y)),
          "r"(__float_as_uint(a.z)), "r"(__float_as_uint(a.w)),
          "r"(__float_as_uint(b.x)), "r"(__float_as_uint(b.y)));
}

// ------------------------------ prep kernels ----------------------------------
// Permuted weight layout: [cb(32)][kt(32)][wm(2)][mi(4)][k8(4)][grp(8)][tig(4)][v(4)]
// v order = (a0,a1,a2,a3) of mma m16n8k8. Gate interleave baked in:
//   q = mi*2 + (v&1); gate = q&3; jhi = q>>2; j = cb*32 + wm*16 + jhi*8 + grp
__global__ void prep_w(const float* __restrict__ src, float* __restrict__ dst) {
    int idx = blockIdx.x * blockDim.x + threadIdx.x;
    if (idx >= 32 * 32 * 4096) return;
    int v   = idx & 3;
    int tig = (idx >> 2) & 3;
    int grp = (idx >> 4) & 7;
    int k8  = (idx >> 7) & 3;
    int mi  = (idx >> 9) & 3;
    int wm  = (idx >> 11) & 1;
    int kt  = (idx >> 12) & 31;
    int cb  = idx >> 17;
    int r8  = v & 1;
    int kh  = (v >> 1) * 4;
    int q   = mi * 2 + r8;
    int gate = q & 3;
    int jhi  = q >> 2;
    int j = cb * 32 + wm * 16 + jhi * 8 + grp;
    int k = kt * 32 + k8 * 8 + tig + kh;
    dst[idx] = src[(size_t)k * FOURH + gate * 1024 + j];
}

// Permuted activation layout: [blk][kt(32)][k8(4)][grp(8)][tig(4)][u(2)]
// (b = blk*8 + grp, k = kt*32 + k8*8 + tig + u*4). m = t*512 + b for x.
__global__ void prep_x(const float* __restrict__ x) {
    int id = blockIdx.x * blockDim.x + threadIdx.x;   // one per 8 floats
    if (id >= MTOT * 1024 / 8) return;
    int grp = id & 7;
    int k8  = (id >> 3) & 3;
    int kt  = (id >> 5) & 31;
    int blk = id >> 10;
    int m = blk * 8 + grp;
    int t = m >> 9, b = m & 511;
    const float* s = x + ((size_t)b * TIME_TOT + t) * FEAT + kt * 32 + k8 * 8;
    float4 lo = *(const float4*)s;
    float4 hi = *(const float4*)(s + 4);
    float* d = g_xp + (size_t)blk * 8192 + kt * 256 + k8 * 64 + grp * 8;
    float4 o0 = {lo.x, hi.x, lo.y, hi.y};
    float4 o1 = {lo.z, hi.z, lo.w, hi.w};
    *(float4*)d = o0;
    *(float4*)(d + 4) = o1;
}

__global__ void init_state() {
    int i = blockIdx.x * blockDim.x + threadIdx.x;
    if (i < BATCH * HIDDEN) { g_hp[0][i] = 0.f; g_c[i] = 0.f; }
}

// ------------------------------ shared GEMM core ------------------------------
// Stage = 32KB: A tile (Wp/Rp, 4096f) @ +0, B tile (xp/hp, 4096f) @ +16KB.
#define ISSUE_STAGE(s, kt) do {                                                   \
    uint32_t _stA = sb + (uint32_t)(s) * 32768u;                                  \
    uint32_t _stB = _stA + 16384u;                                                \
    const float* _as = Aperm + (size_t)(kt) * 4096;                               \
    _Pragma("unroll")                                                             \
    for (int _r = 0; _r < 4; _r++) {                                              \
        int _id = tid + _r * 256;                                                 \
        CP16(_stA + _id * 16, _as + _id * 4);                                     \
    }                                                                             \
    _Pragma("unroll")                                                             \
    for (int _r = 0; _r < 4; _r++) {                                              \
        int _id = tid + _r * 256;                                                 \
        int _ch = _id >> 6, _in = _id & 63;                                       \
        CP16(_stB + _ch * 1024 + _in * 16,                                        \
             Bperm + (size_t)_ch * 8192 + (size_t)(kt) * 256 + _in * 4);          \
    }                                                                             \
} while (0)

#define COMPUTE_STAGE(s) do {                                                     \
    uint32_t _aB = sb + (uint32_t)(s) * 32768u + wm * 8192u + grp * 64u + tig * 16u; \
    uint32_t _bB = sb + (uint32_t)(s) * 32768u + 16384u + wn * 4096u + grp * 32u + tig * 8u; \
    _Pragma("unroll")                                                             \
    for (int _k8 = 0; _k8 < 4; _k8++) {                                           \
        float4 _af[4]; float2 _bf[4];                                             \
        _Pragma("unroll")                                                         \
        for (int _mi = 0; _mi < 4; _mi++)                                         \
            _af[_mi] = lds128(_aB + _mi * 2048 + _k8 * 512);                      \
        _Pragma("unroll")                                                         \
        for (int _nj = 0; _nj < 4; _nj++)                                         \
            _bf[_nj] = lds64(_bB + _nj * 1024 + _k8 * 256);                       \
        _Pragma("unroll")                                                         \
        for (int _mi = 0; _mi < 4; _mi++)                                         \
            _Pragma("unroll")                                                     \
            for (int _nj = 0; _nj < 4; _nj++)                                     \
                mma_tf32(acc[_mi][_nj], _af[_mi], _bf[_nj]);                      \
    }                                                                             \
} while (0)

#define GEMM_MAIN() do {                                                          \
    ISSUE_STAGE(0, 0); CP_COMMIT();                                               \
    ISSUE_STAGE(1, 1); CP_COMMIT();                                               \
    ISSUE_STAGE(2, 2); CP_COMMIT();                                               \
    for (int kt = 0; kt < 32; kt++) {                                             \
        CP_WAIT2();                                                               \
        __syncthreads();                                                          \
        if (kt + 3 < 32) ISSUE_STAGE((kt + 3) & 3, kt + 3);                       \
        CP_COMMIT();                                                              \
        COMPUTE_STAGE(kt & 3);                                                    \
    }                                                                             \
} while (0)

// ------------------------------ big GEMM: zxp = x @ W + bias ------------------
// grid (32, 400): cb = weight strip, by -> 128 m-rows (blk0 = by*16).
__global__ void __launch_bounds__(256, 1)
gemm_big(const float* __restrict__ bias)
{
    extern __shared__ char smem[];
    const uint32_t sb = (uint32_t)__cvta_generic_to_shared(smem);
    const int tid = threadIdx.x, lane = tid & 31, wid = tid >> 5;
    const int wm = wid >> 2, wn = wid & 3;
    const int grp = lane >> 2, tig = lane & 3;
    const int cb = blockIdx.x, by = blockIdx.y;

    const float* Aperm = g_Wp + (size_t)cb * 131072;
    const float* Bperm = g_xp + (size_t)(by * 16) * 8192;

    float acc[4][4][4];
#pragma unroll
    for (int a = 0; a < 4; a++)
#pragma unroll
        for (int b = 0; b < 4; b++)
#pragma unroll
            for (int c = 0; c < 4; c++) acc[a][b][c] = 0.f;

    GEMM_MAIN();

    const int j0 = cb * 32 + wm * 16;
#pragma unroll
    for (int jhi = 0; jhi < 2; jhi++) {
        const int j = j0 + jhi * 8 + grp;
        const float b0 = __ldg(bias + j);
        const float b1 = __ldg(bias + 1024 + j);
        const float b2 = __ldg(bias + 2048 + j);
        const float b3 = __ldg(bias + 3072 + j);
#pragma unroll
        for (int nj = 0; nj < 4; nj++) {
#pragma unroll
            for (int e = 0; e < 2; e++) {
                const int m = (by * 16 + wn * 4 + nj) * 8 + tig * 2 + e;
                float4 z;
                z.x = acc[2 * jhi    ][nj][e]     + b0;
                z.y = acc[2 * jhi    ][nj][2 + e] + b1;
                z.z = acc[2 * jhi + 1][nj][e]     + b2;
                z.w = acc[2 * jhi + 1][nj][2 + e] + b3;
                *(float4*)(g_zxp + (size_t)m * 4096 + j * 4) = z;
            }
        }
    }
}

// ------------------------------ recurrent step --------------------------------
// grid (32, 4): cb = hidden strip (32 j), by -> 128 batch rows.
__global__ void __launch_bounds__(256, 1)
lstm_step(float* __restrict__ out, int t)
{
    extern __shared__ char smem[];
    const uint32_t sb = (uint32_t)__cvta_generic_to_shared(smem);
    const int tid = threadIdx.x, lane = tid & 31, wid = tid >> 5;
    const int wm = wid >> 2, wn = wid & 3;
    const int grp = lane >> 2, tig = lane & 3;
    const int cb = blockIdx.x, by = blockIdx.y;

    const float* Aperm = g_Rp + (size_t)cb * 131072;
    const float* Bperm = g_hp[t & 1] + (size_t)(by * 16) * 8192;
    float* hw = g_hp[(t & 1) ^ 1];

    float acc[4][4][4];
#pragma unroll
    for (int a = 0; a < 4; a++)
#pragma unroll
        for (int b = 0; b < 4; b++)
#pragma unroll
            for (int c = 0; c < 4; c++) acc[a][b][c] = 0.f;

    GEMM_MAIN();

    // fused LSTM epilogue
    const int j0 = cb * 32 + wm * 16;
#pragma unroll
    for (int jhi = 0; jhi < 2; jhi++) {
        const int j = j0 + jhi * 8 + grp;
        // hp-write index pieces for this j
        const int kt_ = j >> 5, rem = j & 31;
        const int k8_ = rem >> 3, rr = rem & 7;
        const int u_ = rr >> 2, tg_ = rr & 3;
        const int joff = kt_ * 256 + k8_ * 64 + tg_ * 2 + u_;
#pragma unroll
        for (int nj = 0; nj < 4; nj++) {
#pragma unroll
            for (int e = 0; e < 2; e++) {
                const int b = (by * 16 + wn * 4 + nj) * 8 + tig * 2 + e;
                const float4 zx = *(const float4*)(g_zxp +
                    ((size_t)(t * 512 + b)) * 4096 + j * 4);
                float zi = acc[2 * jhi    ][nj][e]     + zx.x;
                float zf = acc[2 * jhi    ][nj][2 + e] + zx.y;
                float zg = acc[2 * jhi + 1][nj][e]     + zx.z;
                float zo = acc[2 * jhi + 1][nj][2 + e] + zx.w;

                float si = 1.f / (1.f + expf(-zi));
                float sf = 1.f / (1.f + expf(-zf));
                float so = 1.f / (1.f + expf(-zo));
                float tg = tanhf(zg);

                const size_t ci = (size_t)b * 1024 + j;
                float cn = sf * g_c[ci] + si * tg;
                float hn = so * tanhf(cn);
                g_c[ci] = cn;
                out[(size_t)b * (TSTEPS * HIDDEN) + (size_t)t * 1024 + j] = hn;
                hw[(size_t)(b >> 3) * 8192 + joff + (b & 7) * 8] = hn;
            }
        }
    }
}

// ------------------------------ launch ----------------------------------------
extern "C" void kernel_launch(void* const* d_in, const int* in_sizes, int n_in,
                              void* d_out, int out_size)
{
    const float* x    = (const float*)d_in[0];  // [512, 103, 1024]
    const float* W    = (const float*)d_in[1];  // [1024, 4096]
    const float* R    = (const float*)d_in[2];  // [1024, 4096]
    const float* bias = (const float*)d_in[3];  // [4096]
    float* out = (float*)d_out;                 // [512, 100, 1024]

    float *Wp, *Rp;
    cudaGetSymbolAddress((void**)&Wp, g_Wp);
    cudaGetSymbolAddress((void**)&Rp, g_Rp);

    cudaFuncSetAttribute(gemm_big,  cudaFuncAttributeMaxDynamicSharedMemorySize, SMEM_SZ);
    cudaFuncSetAttribute(lstm_step, cudaFuncAttributeMaxDynamicSharedMemorySize, SMEM_SZ);

    prep_w<<<(32 * 32 * 4096) / 256, 256>>>(W, Wp);
    prep_w<<<(32 * 32 * 4096) / 256, 256>>>(R, Rp);
    prep_x<<<(MTOT * 1024 / 8) / 256, 256>>>(x);
    init_state<<<(BATCH * HIDDEN + 255) / 256, 256>>>();

    dim3 gridBig(32, MTOT / 128);     // (32, 400)
    gemm_big<<<gridBig, 256, SMEM_SZ>>>(bias);

    dim3 gridStep(32, BATCH / 128);   // (32, 4)
    for (int t = 0; t < TSTEPS; t++)
        lstm_step<<<gridStep, 256, SMEM_SZ>>>(out, t);
}

// round 5
// speedup vs baseline: 4.8337x; 1.5320x over previous
#include <cuda_runtime.h>
#include <cuda_fp16.h>
#include <cstdint>
#include <math.h>

#define HIDDEN   1024
#define BATCH    512
#define FEAT     1024
#define TSTEPS   100
#define TIME_TOT 103
#define FOURH    4096
#define MTOT     (TSTEPS * BATCH)   // 51200

// stage = A 16KB + B 16KB; 4 stages
#define STAGE_B  32768
#define SMEM_SZ  (4 * STAGE_B)      // 131072

// ------------------------------ scratch (device globals, no allocs) ----------
__device__ __align__(16) __half g_Wp[32 * 16 * 8192];          // permuted W fp16 (8MB)
__device__ __align__(16) __half g_Rp[32 * 16 * 8192];          // permuted R fp16 (8MB)
__device__ __align__(16) __half g_xp[(size_t)MTOT * 1024];     // permuted x fp16 (100MB)
__device__ __align__(16) float  g_zxp[(size_t)MTOT * 4096];    // x@W+b gate-packed fp32
__device__ __align__(16) __half g_hp[2][BATCH * HIDDEN];       // permuted h fp16 ping-pong
__device__ __align__(16) float  g_c [BATCH * HIDDEN];

// ------------------------------ asm helpers ----------------------------------
#define CP16(dst, src) \
    asm volatile("cp.async.cg.shared.global [%0], [%1], 16;" :: "r"(dst), "l"(src))
#define CP_COMMIT() asm volatile("cp.async.commit_group;" ::: "memory")
#define CP_WAIT2()  asm volatile("cp.async.wait_group 2;" ::: "memory")

__device__ __forceinline__ uint4 lds128u(uint32_t a) {
    uint4 v;
    asm volatile("ld.shared.v4.b32 {%0,%1,%2,%3}, [%4];"
                 : "=r"(v.x), "=r"(v.y), "=r"(v.z), "=r"(v.w) : "r"(a));
    return v;
}
__device__ __forceinline__ uint2 lds64u(uint32_t a) {
    uint2 v;
    asm volatile("ld.shared.v2.b32 {%0,%1}, [%2];" : "=r"(v.x), "=r"(v.y) : "r"(a));
    return v;
}
__device__ __forceinline__ void mma_f16(float c[4], uint4 a, uint2 b) {
    asm volatile(
        "mma.sync.aligned.m16n8k16.row.col.f32.f16.f16.f32 "
        "{%0,%1,%2,%3}, {%4,%5,%6,%7}, {%8,%9}, {%0,%1,%2,%3};"
        : "+f"(c[0]), "+f"(c[1]), "+f"(c[2]), "+f"(c[3])
        : "r"(a.x), "r"(a.y), "r"(a.z), "r"(a.w), "r"(b.x), "r"(b.y));
}

// ------------------------------ prep kernels ----------------------------------
// Weight layout (half2 units): [cb(32)][kt(16)][wm(2)][mi(4)][k16(4)][grp(8)][tig(4)][v(4)]
// v: r8=v&1 (row grp vs grp+8), khi=(v>>1)*8.  q=mi*2+r8: gate=q&3, jhi=q>>2.
// j = cb*32 + wm*16 + jhi*8 + grp;  k = kt*64 + k16*16 + khi + 2*tig (+1 in .y)
__global__ void prep_w(const float* __restrict__ src, __half2* __restrict__ dst) {
    int idx = blockIdx.x * blockDim.x + threadIdx.x;
    if (idx >= 32 * 16 * 4096) return;
    int v   = idx & 3;
    int tig = (idx >> 2) & 3;
    int grp = (idx >> 4) & 7;
    int k16 = (idx >> 7) & 3;
    int mi  = (idx >> 9) & 3;
    int wm  = (idx >> 11) & 1;
    int kt  = (idx >> 12) & 15;
    int cb  = idx >> 16;
    int r8  = v & 1;
    int khi = (v >> 1) * 8;
    int q   = mi * 2 + r8;
    int gate = q & 3;
    int jhi  = q >> 2;
    int j = cb * 32 + wm * 16 + jhi * 8 + grp;
    int k = kt * 64 + k16 * 16 + khi + 2 * tig;
    int col = gate * 1024 + j;
    dst[idx] = __floats2half2_rn(src[(size_t)k * FOURH + col],
                                 src[(size_t)(k + 1) * FOURH + col]);
}

// Activation layout (half2 units): [blk(m/8)][kt(16)][k16(4)][grp(8)][tig(4)][reg(2)]
// value = {act[b][k], act[b][k+1]}, k = kt*64 + k16*16 + reg*8 + 2*tig, b = blk*8+grp
__global__ void prep_x(const float* __restrict__ x, __half2* __restrict__ xp) {
    int id = blockIdx.x * blockDim.x + threadIdx.x;   // one per 16 floats
    if (id >= MTOT * 1024 / 16) return;
    int grp = id & 7;
    int k16 = (id >> 3) & 3;
    int kt  = (id >> 5) & 15;
    int blk = id >> 9;
    int m = blk * 8 + grp;
    int t = m >> 9, bb = m & 511;
    const float* s = x + ((size_t)bb * TIME_TOT + t) * FEAT + kt * 64 + k16 * 16;
    float f[16];
#pragma unroll
    for (int q = 0; q < 4; q++) *(float4*)(f + q * 4) = *(const float4*)(s + q * 4);
    __half2 o[8];
#pragma unroll
    for (int tg = 0; tg < 4; tg++)
#pragma unroll
        for (int rg = 0; rg < 2; rg++)
            o[tg * 2 + rg] = __floats2half2_rn(f[rg * 8 + 2 * tg], f[rg * 8 + 2 * tg + 1]);
    __half2* d = xp + (size_t)blk * 4096 + kt * 256 + k16 * 64 + grp * 8;
    *(uint4*)d = *(uint4*)o;
    *(uint4*)(d + 4) = *(uint4*)(o + 4);
}

__global__ void init_state() {
    int i = blockIdx.x * blockDim.x + threadIdx.x;
    if (i < BATCH * HIDDEN / 2) ((uint32_t*)g_hp[0])[i] = 0u;
    if (i < BATCH * HIDDEN) g_c[i] = 0.f;
}

// ------------------------------ shared GEMM core (K = 1024, BK = 64) ----------
#define ISSUE_STAGE(s, kt) do {                                                   \
    uint32_t _stA = sb + (uint32_t)(s) * STAGE_B;                                 \
    uint32_t _stB = _stA + 16384u;                                                \
    const char* _as = Abase + (size_t)(kt) * 16384;                               \
    _Pragma("unroll")                                                             \
    for (int _r = 0; _r < 4; _r++) {                                              \
        int _id = tid + _r * 256;                                                 \
        CP16(_stA + _id * 16, _as + _id * 16);                                    \
    }                                                                             \
    _Pragma("unroll")                                                             \
    for (int _r = 0; _r < 4; _r++) {                                              \
        int _id = tid + _r * 256;                                                 \
        int _bk = _id >> 6, _in = _id & 63;                                       \
        CP16(_stB + _id * 16,                                                     \
             Bbase + (size_t)_bk * 16384 + (size_t)(kt) * 1024 + _in * 16);       \
    }                                                                             \
} while (0)

#define COMPUTE_STAGE(s) do {                                                     \
    uint32_t _aB = sb + (uint32_t)(s) * STAGE_B + wm * 8192u + grp * 64u + tig * 16u; \
    uint32_t _bB = sb + (uint32_t)(s) * STAGE_B + 16384u + wn * 4096u + grp * 32u + tig * 8u; \
    _Pragma("unroll")                                                             \
    for (int _k = 0; _k < 4; _k++) {                                              \
        uint4 _af[4]; uint2 _bf[4];                                               \
        _Pragma("unroll")                                                         \
        for (int _mi = 0; _mi < 4; _mi++)                                         \
            _af[_mi] = lds128u(_aB + _mi * 2048 + _k * 512);                      \
        _Pragma("unroll")                                                         \
        for (int _nj = 0; _nj < 4; _nj++)                                         \
            _bf[_nj] = lds64u(_bB + _nj * 1024 + _k * 256);                       \
        _Pragma("unroll")                                                         \
        for (int _mi = 0; _mi < 4; _mi++)                                         \
            _Pragma("unroll")                                                     \
            for (int _nj = 0; _nj < 4; _nj++)                                     \
                mma_f16(acc[_mi][_nj], _af[_mi], _bf[_nj]);                       \
    }                                                                             \
} while (0)

#define GEMM_MAIN() do {                                                          \
    ISSUE_STAGE(0, 0); CP_COMMIT();                                               \
    ISSUE_STAGE(1, 1); CP_COMMIT();                                               \
    ISSUE_STAGE(2, 2); CP_COMMIT();                                               \
    for (int kt = 0; kt < 16; kt++) {                                             \
        CP_WAIT2();                                                               \
        __syncthreads();                                                          \
        if (kt + 3 < 16) ISSUE_STAGE((kt + 3) & 3, kt + 3);                       \
        CP_COMMIT();                                                              \
        COMPUTE_STAGE(kt & 3);                                                    \
    }                                                                             \
} while (0)

// ------------------------------ big GEMM: zxp = x @ W + bias ------------------
__global__ void __launch_bounds__(256, 1)
gemm_big(const float* __restrict__ bias)
{
    extern __shared__ char smem[];
    const uint32_t sb = (uint32_t)__cvta_generic_to_shared(smem);
    const int tid = threadIdx.x, lane = tid & 31, wid = tid >> 5;
    const int wm = wid >> 2, wn = wid & 3;
    const int grp = lane >> 2, tig = lane & 3;
    const int cb = blockIdx.x, by = blockIdx.y;

    const char* Abase = (const char*)g_Wp + (size_t)cb * 262144;
    const char* Bbase = (const char*)g_xp + (size_t)(by * 16) * 16384;

    float acc[4][4][4];
#pragma unroll
    for (int a = 0; a < 4; a++)
#pragma unroll
        for (int b = 0; b < 4; b++)
#pragma unroll
            for (int c = 0; c < 4; c++) acc[a][b][c] = 0.f;

    GEMM_MAIN();

    const int j0 = cb * 32 + wm * 16;
#pragma unroll
    for (int jhi = 0; jhi < 2; jhi++) {
        const int j = j0 + jhi * 8 + grp;
        const float b0 = __ldg(bias + j);
        const float b1 = __ldg(bias + 1024 + j);
        const float b2 = __ldg(bias + 2048 + j);
        const float b3 = __ldg(bias + 3072 + j);
#pragma unroll
        for (int nj = 0; nj < 4; nj++) {
#pragma unroll
            for (int e = 0; e < 2; e++) {
                const int m = (by * 16 + wn * 4 + nj) * 8 + tig * 2 + e;
                float4 z;
                z.x = acc[2 * jhi    ][nj][e]     + b0;
                z.y = acc[2 * jhi    ][nj][2 + e] + b1;
                z.z = acc[2 * jhi + 1][nj][e]     + b2;
                z.w = acc[2 * jhi + 1][nj][2 + e] + b3;
                *(float4*)(g_zxp + (size_t)m * 4096 + j * 4) = z;
            }
        }
    }
}

// ------------------------------ recurrent step --------------------------------
__global__ void __launch_bounds__(256, 1)
lstm_step(float* __restrict__ out, int t)
{
    extern __shared__ char smem[];
    const uint32_t sb = (uint32_t)__cvta_generic_to_shared(smem);
    const int tid = threadIdx.x, lane = tid & 31, wid = tid >> 5;
    const int wm = wid >> 2, wn = wid & 3;
    const int grp = lane >> 2, tig = lane & 3;
    const int cb = blockIdx.x, by = blockIdx.y;

    const char* Abase = (const char*)g_Rp + (size_t)cb * 262144;
    const char* Bbase = (const char*)g_hp[t & 1] + (size_t)(by * 16) * 16384;
    __half* hw = g_hp[(t & 1) ^ 1];

    float acc[4][4][4];
#pragma unroll
    for (int a = 0; a < 4; a++)
#pragma unroll
        for (int b = 0; b < 4; b++)
#pragma unroll
            for (int c = 0; c < 4; c++) acc[a][b][c] = 0.f;

    GEMM_MAIN();

    // fused LSTM epilogue
    const int j0 = cb * 32 + wm * 16;
#pragma unroll
    for (int jhi = 0; jhi < 2; jhi++) {
        const int j = j0 + jhi * 8 + grp;
        // hp layout decomposition of j: k = kt*64 + k16*16 + reg*8 + 2*tig + u
        const int kt_  = j >> 6;
        const int k16_ = (j >> 4) & 3;
        const int reg_ = (j >> 3) & 1;
        const int tig_ = (j >> 1) & 3;
        const int u_   = j & 1;
        const int jbase = ((kt_ * 4 + k16_) * 8) * 4;   // add grp_b*4 + tig_ later
#pragma unroll
        for (int nj = 0; nj < 4; nj++) {
            const int blk = by * 16 + wn * 4 + nj;
#pragma unroll
            for (int e = 0; e < 2; e++) {
                const int grp_b = tig * 2 + e;
                const int b = blk * 8 + grp_b;
                const float4 zx = *(const float4*)(g_zxp +
                    ((size_t)(t * 512 + b)) * 4096 + j * 4);
                float zi = acc[2 * jhi    ][nj][e]     + zx.x;
                float zf = acc[2 * jhi    ][nj][2 + e] + zx.y;
                float zg = acc[2 * jhi + 1][nj][e]     + zx.z;
                float zo = acc[2 * jhi + 1][nj][2 + e] + zx.w;

                float si = 1.f / (1.f + expf(-zi));
                float sf = 1.f / (1.f + expf(-zf));
                float so = 1.f / (1.f + expf(-zo));
                float tg = tanhf(zg);

                const size_t ci = (size_t)b * 1024 + j;
                float cn = sf * g_c[ci] + si * tg;
                float hn = so * tanhf(cn);
                g_c[ci] = cn;
                out[(size_t)b * (TSTEPS * HIDDEN) + (size_t)t * 1024 + j] = hn;
                hw[(size_t)blk * 8192 + (jbase + grp_b * 4 + tig_) * 4 + reg_ * 2 + u_] =
                    __float2half_rn(hn);
            }
        }
    }
}

// ------------------------------ launch ----------------------------------------
extern "C" void kernel_launch(void* const* d_in, const int* in_sizes, int n_in,
                              void* d_out, int out_size)
{
    const float* x    = (const float*)d_in[0];  // [512, 103, 1024]
    const float* W    = (const float*)d_in[1];  // [1024, 4096]
    const float* R    = (const float*)d_in[2];  // [1024, 4096]
    const float* bias = (const float*)d_in[3];  // [4096]
    float* out = (float*)d_out;                 // [512, 100, 1024]

    __half *Wp, *Rp, *xp;
    cudaGetSymbolAddress((void**)&Wp, g_Wp);
    cudaGetSymbolAddress((void**)&Rp, g_Rp);
    cudaGetSymbolAddress((void**)&xp, g_xp);

    cudaFuncSetAttribute(gemm_big,  cudaFuncAttributeMaxDynamicSharedMemorySize, SMEM_SZ);
    cudaFuncSetAttribute(lstm_step, cudaFuncAttributeMaxDynamicSharedMemorySize, SMEM_SZ);

    prep_w<<<(32 * 16 * 4096) / 256, 256>>>(W, (__half2*)Wp);
    prep_w<<<(32 * 16 * 4096) / 256, 256>>>(R, (__half2*)Rp);
    prep_x<<<(MTOT * 1024 / 16) / 256, 256>>>(x, (__half2*)xp);
    init_state<<<(BATCH * HIDDEN + 255) / 256, 256>>>();

    dim3 gridBig(32, MTOT / 128);     // (32, 400)
    gemm_big<<<gridBig, 256, SMEM_SZ>>>(bias);

    dim3 gridStep(32, BATCH / 128);   // (32, 4)
    for (int t = 0; t < TSTEPS; t++)
        lstm_step<<<gridStep, 256, SMEM_SZ>>>(out, t);
}

// round 6
// speedup vs baseline: 7.0253x; 1.4534x over previous
#include <cuda_runtime.h>
#include <cuda_fp16.h>
#include <cstdint>
#include <math.h>

#define HIDDEN   1024
#define BATCH    512
#define FEAT     1024
#define TSTEPS   100
#define TIME_TOT 103
#define FOURH    4096
#define MTOT     (TSTEPS * BATCH)   // 51200
#define NCTA     128

#define STAGE_B  32768
#define SMEM_SZ  (4 * STAGE_B)      // 131072

// ------------------------------ scratch (device globals, no allocs) ----------
__device__ __align__(16) __half g_WRp[32 * 32 * 8192];         // [W;R] fp16, per-strip (16MB)
__device__ __align__(16) __half g_xp[(size_t)MTOT * 1024];     // permuted x fp16 (100MB)
__device__ __align__(16) __half g_hp[2][BATCH * HIDDEN];       // permuted h fp16 ping-pong
__device__ unsigned g_sync;                                    // grid barrier counter

// ------------------------------ asm helpers ----------------------------------
#define CP16(dst, src) \
    asm volatile("cp.async.cg.shared.global [%0], [%1], 16;" :: "r"(dst), "l"(src))
#define CP_COMMIT() asm volatile("cp.async.commit_group;" ::: "memory")
#define CP_WAIT2()  asm volatile("cp.async.wait_group 2;" ::: "memory")

__device__ __forceinline__ uint4 lds128u(uint32_t a) {
    uint4 v;
    asm volatile("ld.shared.v4.b32 {%0,%1,%2,%3}, [%4];"
                 : "=r"(v.x), "=r"(v.y), "=r"(v.z), "=r"(v.w) : "r"(a));
    return v;
}
__device__ __forceinline__ uint2 lds64u(uint32_t a) {
    uint2 v;
    asm volatile("ld.shared.v2.b32 {%0,%1}, [%2];" : "=r"(v.x), "=r"(v.y) : "r"(a));
    return v;
}
__device__ __forceinline__ void mma_f16(float c[4], uint4 a, uint2 b) {
    asm volatile(
        "mma.sync.aligned.m16n8k16.row.col.f32.f16.f16.f32 "
        "{%0,%1,%2,%3}, {%4,%5,%6,%7}, {%8,%9}, {%0,%1,%2,%3};"
        : "+f"(c[0]), "+f"(c[1]), "+f"(c[2]), "+f"(c[3])
        : "r"(a.x), "r"(a.y), "r"(a.z), "r"(a.w), "r"(b.x), "r"(b.y));
}

// ------------------------------ prep (single launch) --------------------------
// WRp layout (half2 units): [cb(32)][kt(32 over K=2048)][wm(2)][mi(4)][k16(4)][grp(8)][tig(4)][v(4)]
// kt<16 -> W rows k=kt*64.., kt>=16 -> R rows k=(kt-16)*64..  Gate interleave:
// q=mi*2+(v&1): gate=q&3, jhi=q>>2; j=cb*32+wm*16+jhi*8+grp; k+=k16*16+(v>>1)*8+2*tig
#define N1 (32 * 32 * 4096)          // WRp half2 elems
#define N2 (MTOT * 1024 / 16)        // xp 16-float chunks
#define N3 (BATCH * HIDDEN / 2)      // hp[0] zero words

__global__ void prep_all(const float* __restrict__ W, const float* __restrict__ R,
                         const float* __restrict__ x)
{
    int idx = blockIdx.x * blockDim.x + threadIdx.x;
    if (idx < N1) {
        int v   = idx & 3;
        int tig = (idx >> 2) & 3;
        int grp = (idx >> 4) & 7;
        int k16 = (idx >> 7) & 3;
        int mi  = (idx >> 9) & 3;
        int wm  = (idx >> 11) & 1;
        int kt  = (idx >> 12) & 31;
        int cb  = idx >> 17;
        int r8  = v & 1;
        int khi = (v >> 1) * 8;
        int q   = mi * 2 + r8;
        int gate = q & 3;
        int jhi  = q >> 2;
        int j = cb * 32 + wm * 16 + jhi * 8 + grp;
        int kl = k16 * 16 + khi + 2 * tig;
        const float* src = (kt < 16) ? W : R;
        int k = (kt < 16 ? kt : kt - 16) * 64 + kl;
        int col = gate * 1024 + j;
        ((__half2*)g_WRp)[idx] = __floats2half2_rn(src[(size_t)k * FOURH + col],
                                                   src[(size_t)(k + 1) * FOURH + col]);
    } else if (idx < N1 + N2) {
        int id = idx - N1;
        int grp = id & 7;
        int k16 = (id >> 3) & 3;
        int kt  = (id >> 5) & 15;
        int blk = id >> 9;
        int m = blk * 8 + grp;
        int t = m >> 9, bb = m & 511;
        const float* s = x + ((size_t)bb * TIME_TOT + t) * FEAT + kt * 64 + k16 * 16;
        float f[16];
#pragma unroll
        for (int qd = 0; qd < 4; qd++) *(float4*)(f + qd * 4) = *(const float4*)(s + qd * 4);
        __half2 o[8];
#pragma unroll
        for (int tg = 0; tg < 4; tg++)
#pragma unroll
            for (int rg = 0; rg < 2; rg++)
                o[tg * 2 + rg] = __floats2half2_rn(f[rg * 8 + 2 * tg], f[rg * 8 + 2 * tg + 1]);
        __half2* d = (__half2*)g_xp + (size_t)blk * 4096 + kt * 256 + k16 * 64 + grp * 8;
        *(uint4*)d = *(uint4*)o;
        *(uint4*)(d + 4) = *(uint4*)(o + 4);
    } else if (idx < N1 + N2 + N3) {
        ((uint32_t*)g_hp)[idx - N1 - N2] = 0u;     // zero hp[0]
    } else if (idx == N1 + N2 + N3) {
        g_sync = 0u;
    }
}

// ------------------------------ pipeline pieces -------------------------------
#define ISSUE_STAGE(s, kt, bxp, bhp) do {                                         \
    uint32_t _stA = sb + (uint32_t)(s) * STAGE_B;                                 \
    uint32_t _stB = _stA + 16384u;                                                \
    const char* _as = Abase + (size_t)(kt) * 16384;                               \
    _Pragma("unroll")                                                             \
    for (int _r = 0; _r < 4; _r++) {                                              \
        int _id = tid + _r * 256;                                                 \
        CP16(_stA + _id * 16, _as + _id * 16);                                    \
    }                                                                             \
    const char* _bsrc = ((kt) < 16) ? ((bxp) + (size_t)(kt) * 1024)               \
                                    : ((bhp) + (size_t)((kt) - 16) * 1024);       \
    _Pragma("unroll")                                                             \
    for (int _r = 0; _r < 4; _r++) {                                              \
        int _id = tid + _r * 256;                                                 \
        int _bk = _id >> 6, _in = _id & 63;                                       \
        CP16(_stB + _id * 16, _bsrc + (size_t)_bk * 16384 + _in * 16);            \
    }                                                                             \
} while (0)

#define COMPUTE_STAGE(s) do {                                                     \
    uint32_t _aB = sb + (uint32_t)(s) * STAGE_B + wm * 8192u + grp * 64u + tig * 16u; \
    uint32_t _bB = sb + (uint32_t)(s) * STAGE_B + 16384u + wn * 4096u + grp * 32u + tig * 8u; \
    _Pragma("unroll")                                                             \
    for (int _k = 0; _k < 4; _k++) {                                              \
        uint4 _af[4]; uint2 _bf[4];                                               \
        _Pragma("unroll")                                                         \
        for (int _mi = 0; _mi < 4; _mi++)                                         \
            _af[_mi] = lds128u(_aB + _mi * 2048 + _k * 512);                      \
        _Pragma("unroll")                                                         \
        for (int _nj = 0; _nj < 4; _nj++)                                         \
            _bf[_nj] = lds64u(_bB + _nj * 1024 + _k * 256);                       \
        _Pragma("unroll")                                                         \
        for (int _mi = 0; _mi < 4; _mi++)                                         \
            _Pragma("unroll")                                                     \
            for (int _nj = 0; _nj < 4; _nj++)                                     \
                mma_f16(acc[_mi][_nj], _af[_mi], _bf[_nj]);                       \
    }                                                                             \
} while (0)

// ------------------------------ persistent fused LSTM -------------------------
// grid (32,4): cb = 32-hidden strip, by = 128-batch block. One CTA/SM, resident.
__global__ void __launch_bounds__(256, 1)
lstm_persist(const float* __restrict__ bias, float* __restrict__ out)
{
    extern __shared__ char smem[];
    const uint32_t sb = (uint32_t)__cvta_generic_to_shared(smem);
    const int tid = threadIdx.x, lane = tid & 31, wid = tid >> 5;
    const int wm = wid >> 2, wn = wid & 3;
    const int grp = lane >> 2, tig = lane & 3;
    const int cb = blockIdx.x, by = blockIdx.y;

    const char* Abase = (const char*)g_WRp + (size_t)cb * 524288;   // 512KB strip

    // bias registers (loop-invariant)
    const int j0 = cb * 32 + wm * 16;
    float bia[2][4];
#pragma unroll
    for (int jhi = 0; jhi < 2; jhi++) {
        const int j = j0 + jhi * 8 + grp;
        bia[jhi][0] = __ldg(bias + j);
        bia[jhi][1] = __ldg(bias + 1024 + j);
        bia[jhi][2] = __ldg(bias + 2048 + j);
        bia[jhi][3] = __ldg(bias + 3072 + j);
    }
    // c state in registers
    float cr[2][4][2];
#pragma unroll
    for (int a = 0; a < 2; a++)
#pragma unroll
        for (int b = 0; b < 4; b++) { cr[a][b][0] = 0.f; cr[a][b][1] = 0.f; }

    // prologue: t=0, x-ktiles 0..2
    {
        const char* Bx = (const char*)g_xp + (size_t)(by * 16) * 16384;
        const char* Bh = (const char*)g_hp[0] + (size_t)(by * 16) * 16384;
        ISSUE_STAGE(0, 0, Bx, Bh); CP_COMMIT();
        ISSUE_STAGE(1, 1, Bx, Bh); CP_COMMIT();
        ISSUE_STAGE(2, 2, Bx, Bh); CP_COMMIT();
    }

    for (int t = 0; t < TSTEPS; t++) {
        const char* Bx = (const char*)g_xp + (size_t)(t * 64 + by * 16) * 16384;
        const char* Bh = (const char*)g_hp[t & 1] + (size_t)(by * 16) * 16384;
        __half* hw = g_hp[(t & 1) ^ 1];

        float acc[4][4][4];
#pragma unroll
        for (int a = 0; a < 4; a++)
#pragma unroll
            for (int b = 0; b < 4; b++)
#pragma unroll
                for (int c = 0; c < 4; c++) acc[a][b][c] = 0.f;

        for (int kt = 0; kt < 32; kt++) {
            CP_WAIT2();
            __syncthreads();
            if (kt + 3 < 32) ISSUE_STAGE((kt + 3) & 3, kt + 3, Bx, Bh);
            CP_COMMIT();
            COMPUTE_STAGE(kt & 3);
        }

        // fused LSTM epilogue (c in registers)
#pragma unroll
        for (int jhi = 0; jhi < 2; jhi++) {
            const int j = j0 + jhi * 8 + grp;
            const int kt_  = j >> 6;
            const int k16_ = (j >> 4) & 3;
            const int reg_ = (j >> 3) & 1;
            const int tig_ = (j >> 1) & 3;
            const int u_   = j & 1;
            const int jbase = (kt_ * 4 + k16_) * 32;
#pragma unroll
            for (int nj = 0; nj < 4; nj++) {
                const int blk = by * 16 + wn * 4 + nj;
#pragma unroll
                for (int e = 0; e < 2; e++) {
                    const int grp_b = tig * 2 + e;
                    const int b = blk * 8 + grp_b;
                    float zi = acc[2 * jhi    ][nj][e]     + bia[jhi][0];
                    float zf = acc[2 * jhi    ][nj][2 + e] + bia[jhi][1];
                    float zg = acc[2 * jhi + 1][nj][e]     + bia[jhi][2];
                    float zo = acc[2 * jhi + 1][nj][2 + e] + bia[jhi][3];

                    float si = 1.f / (1.f + expf(-zi));
                    float sf = 1.f / (1.f + expf(-zf));
                    float so = 1.f / (1.f + expf(-zo));
                    float tg = tanhf(zg);

                    float cn = sf * cr[jhi][nj][e] + si * tg;
                    float hn = so * tanhf(cn);
                    cr[jhi][nj][e] = cn;
                    out[(size_t)b * (TSTEPS * HIDDEN) + (size_t)t * 1024 + j] = hn;
                    hw[(size_t)blk * 8192 + (jbase + grp_b * 4 + tig_) * 4 + reg_ * 2 + u_] =
                        __float2half_rn(hn);
                }
            }
        }

        __syncthreads();   // all warps done with smem

        // prefetch next step's x-ktiles 0..2 BEFORE the barrier (no h dependency)
        if (t + 1 < TSTEPS) {
            const char* Bx2 = (const char*)g_xp + (size_t)((t + 1) * 64 + by * 16) * 16384;
            ISSUE_STAGE(0, 0, Bx2, Bh); CP_COMMIT();
            ISSUE_STAGE(1, 1, Bx2, Bh); CP_COMMIT();
            ISSUE_STAGE(2, 2, Bx2, Bh); CP_COMMIT();
        }

        // grid barrier (monotonic counter; h writes fenced before arrive)
        if (tid == 0) {
            __threadfence();
            atomicAdd(&g_sync, 1u);
            const unsigned tgt = (unsigned)(t + 1) * NCTA;
            while (*(volatile unsigned*)&g_sync < tgt) { }
        }
        __syncthreads();
    }
}

// ------------------------------ launch ----------------------------------------
extern "C" void kernel_launch(void* const* d_in, const int* in_sizes, int n_in,
                              void* d_out, int out_size)
{
    const float* x    = (const float*)d_in[0];  // [512, 103, 1024]
    const float* W    = (const float*)d_in[1];  // [1024, 4096]
    const float* R    = (const float*)d_in[2];  // [1024, 4096]
    const float* bias = (const float*)d_in[3];  // [4096]
    float* out = (float*)d_out;                 // [512, 100, 1024]

    cudaFuncSetAttribute(lstm_persist, cudaFuncAttributeMaxDynamicSharedMemorySize, SMEM_SZ);

    const int total = N1 + N2 + N3 + 1;
    prep_all<<<(total + 255) / 256, 256>>>(W, R, x);

    dim3 grid(32, 4);   // 128 CTAs, 1/SM, co-resident
    lstm_persist<<<grid, 256, SMEM_SZ>>>(bias, out);
}

// round 7
// speedup vs baseline: 7.5570x; 1.0757x over previous
#include <cuda_runtime.h>
#include <cuda_fp16.h>
#include <cstdint>
#include <math.h>

#define HIDDEN   1024
#define BATCH    512
#define FEAT     1024
#define TSTEPS   100
#define TIME_TOT 103
#define FOURH    4096
#define MTOT     (TSTEPS * BATCH)   // 51200

#define STAGE_B  32768
#define SMEM_SZ  (4 * STAGE_B)      // 131072

// ------------------------------ scratch (device globals, no allocs) ----------
__device__ __align__(16) __half g_WRp[32 * 32 * 8192];         // [W;R] fp16 per-strip (16MB)
__device__ __align__(16) __half g_xp[(size_t)MTOT * 1024];     // permuted x fp16 (100MB)
__device__ __align__(16) __half g_hp[2][BATCH * HIDDEN];       // permuted h fp16 ping-pong
__device__ unsigned g_sync4[4];                                // per-by-group barrier counters

// ------------------------------ asm helpers ----------------------------------
#define CP16(dst, src) \
    asm volatile("cp.async.cg.shared.global [%0], [%1], 16;" :: "r"(dst), "l"(src))
#define CP_COMMIT() asm volatile("cp.async.commit_group;" ::: "memory")
#define CP_WAIT2()  asm volatile("cp.async.wait_group 2;" ::: "memory")

__device__ __forceinline__ uint4 lds128u(uint32_t a) {
    uint4 v;
    asm volatile("ld.shared.v4.b32 {%0,%1,%2,%3}, [%4];"
                 : "=r"(v.x), "=r"(v.y), "=r"(v.z), "=r"(v.w) : "r"(a));
    return v;
}
__device__ __forceinline__ uint2 lds64u(uint32_t a) {
    uint2 v;
    asm volatile("ld.shared.v2.b32 {%0,%1}, [%2];" : "=r"(v.x), "=r"(v.y) : "r"(a));
    return v;
}
__device__ __forceinline__ void mma_f16(float c[4], uint4 a, uint2 b) {
    asm volatile(
        "mma.sync.aligned.m16n8k16.row.col.f32.f16.f16.f32 "
        "{%0,%1,%2,%3}, {%4,%5,%6,%7}, {%8,%9}, {%0,%1,%2,%3};"
        : "+f"(c[0]), "+f"(c[1]), "+f"(c[2]), "+f"(c[3])
        : "r"(a.x), "r"(a.y), "r"(a.z), "r"(a.w), "r"(b.x), "r"(b.y));
}

// fast transcendentals (2-ulp __expf; saturating edge cases verified)
__device__ __forceinline__ float sigm_f(float z) {
    return __fdividef(1.f, 1.f + __expf(-z));
}
__device__ __forceinline__ float tanh_f(float z) {
    return 1.f - __fdividef(2.f, __expf(2.f * z) + 1.f);
}

// ------------------------------ prep (single launch) --------------------------
#define N1 (32 * 32 * 4096)          // WRp half2 elems
#define N2 (MTOT * 1024 / 16)        // xp 16-float chunks
#define N3 (BATCH * HIDDEN / 2)      // hp[0] zero words

__global__ void prep_all(const float* __restrict__ W, const float* __restrict__ R,
                         const float* __restrict__ x)
{
    int idx = blockIdx.x * blockDim.x + threadIdx.x;
    if (idx < N1) {
        int v   = idx & 3;
        int tig = (idx >> 2) & 3;
        int grp = (idx >> 4) & 7;
        int k16 = (idx >> 7) & 3;
        int mi  = (idx >> 9) & 3;
        int wm  = (idx >> 11) & 1;
        int kt  = (idx >> 12) & 31;
        int cb  = idx >> 17;
        int r8  = v & 1;
        int khi = (v >> 1) * 8;
        int q   = mi * 2 + r8;
        int gate = q & 3;
        int jhi  = q >> 2;
        int j = cb * 32 + wm * 16 + jhi * 8 + grp;
        int kl = k16 * 16 + khi + 2 * tig;
        const float* src = (kt < 16) ? W : R;
        int k = (kt < 16 ? kt : kt - 16) * 64 + kl;
        int col = gate * 1024 + j;
        ((__half2*)g_WRp)[idx] = __floats2half2_rn(src[(size_t)k * FOURH + col],
                                                   src[(size_t)(k + 1) * FOURH + col]);
    } else if (idx < N1 + N2) {
        int id = idx - N1;
        int grp = id & 7;
        int k16 = (id >> 3) & 3;
        int kt  = (id >> 5) & 15;
        int blk = id >> 9;
        int m = blk * 8 + grp;
        int t = m >> 9, bb = m & 511;
        const float* s = x + ((size_t)bb * TIME_TOT + t) * FEAT + kt * 64 + k16 * 16;
        float f[16];
#pragma unroll
        for (int qd = 0; qd < 4; qd++) *(float4*)(f + qd * 4) = *(const float4*)(s + qd * 4);
        __half2 o[8];
#pragma unroll
        for (int tg = 0; tg < 4; tg++)
#pragma unroll
            for (int rg = 0; rg < 2; rg++)
                o[tg * 2 + rg] = __floats2half2_rn(f[rg * 8 + 2 * tg], f[rg * 8 + 2 * tg + 1]);
        __half2* d = (__half2*)g_xp + (size_t)blk * 4096 + kt * 256 + k16 * 64 + grp * 8;
        *(uint4*)d = *(uint4*)o;
        *(uint4*)(d + 4) = *(uint4*)(o + 4);
    } else if (idx < N1 + N2 + N3) {
        ((uint32_t*)g_hp)[idx - N1 - N2] = 0u;     // zero hp[0] (t=0 h-phase reads it)
    } else if (idx < N1 + N2 + N3 + 4) {
        g_sync4[idx - N1 - N2 - N3] = 0u;          // reset barrier counters every call
    }
}

// ------------------------------ pipeline pieces -------------------------------
#define ISSUE_STAGE(s, kt, bxp, bhp) do {                                         \
    uint32_t _stA = sb + (uint32_t)(s) * STAGE_B;                                 \
    uint32_t _stB = _stA + 16384u;                                                \
    const char* _as = Abase + (size_t)(kt) * 16384;                               \
    _Pragma("unroll")                                                             \
    for (int _r = 0; _r < 4; _r++) {                                              \
        int _id = tid + _r * 256;                                                 \
        CP16(_stA + _id * 16, _as + _id * 16);                                    \
    }                                                                             \
    const char* _bsrc = ((kt) < 16) ? ((bxp) + (size_t)(kt) * 1024)               \
                                    : ((bhp) + (size_t)((kt) - 16) * 1024);       \
    _Pragma("unroll")                                                             \
    for (int _r = 0; _r < 4; _r++) {                                              \
        int _id = tid + _r * 256;                                                 \
        int _bk = _id >> 6, _in = _id & 63;                                       \
        CP16(_stB + _id * 16, _bsrc + (size_t)_bk * 16384 + _in * 16);            \
    }                                                                             \
} while (0)

#define COMPUTE_STAGE(s) do {                                                     \
    uint32_t _aB = sb + (uint32_t)(s) * STAGE_B + wm * 8192u + grp * 64u + tig * 16u; \
    uint32_t _bB = sb + (uint32_t)(s) * STAGE_B + 16384u + wn * 4096u + grp * 32u + tig * 8u; \
    _Pragma("unroll")                                                             \
    for (int _k = 0; _k < 4; _k++) {                                              \
        uint4 _af[4]; uint2 _bf[4];                                               \
        _Pragma("unroll")                                                         \
        for (int _mi = 0; _mi < 4; _mi++)                                         \
            _af[_mi] = lds128u(_aB + _mi * 2048 + _k * 512);                      \
        _Pragma("unroll")                                                         \
        for (int _nj = 0; _nj < 4; _nj++)                                         \
            _bf[_nj] = lds64u(_bB + _nj * 1024 + _k * 256);                       \
        _Pragma("unroll")                                                         \
        for (int _mi = 0; _mi < 4; _mi++)                                         \
            _Pragma("unroll")                                                     \
            for (int _nj = 0; _nj < 4; _nj++)                                     \
                mma_f16(acc[_mi][_nj], _af[_mi], _bf[_nj]);                       \
    }                                                                             \
} while (0)

// ------------------------------ persistent fused LSTM -------------------------
// grid (32,4): cb = 32-hidden strip, by = 128-batch block. 1 CTA/SM, resident.
// Per step: ktiles 0..15 = x_t@W (barrier-independent), 16..31 = h_t@R.
// Barrier wait injected at ktile 13 — hidden behind ~7us of x-compute.
__global__ void __launch_bounds__(256, 1)
lstm_persist(const float* __restrict__ bias, float* __restrict__ out)
{
    extern __shared__ char smem[];
    const uint32_t sb = (uint32_t)__cvta_generic_to_shared(smem);
    const int tid = threadIdx.x, lane = tid & 31, wid = tid >> 5;
    const int wm = wid >> 2, wn = wid & 3;
    const int grp = lane >> 2, tig = lane & 3;
    const int cb = blockIdx.x, by = blockIdx.y;

    const char* Abase = (const char*)g_WRp + (size_t)cb * 524288;

    // loop-invariant bias registers
    const int j0 = cb * 32 + wm * 16;
    float bia[2][4];
#pragma unroll
    for (int jhi = 0; jhi < 2; jhi++) {
        const int j = j0 + jhi * 8 + grp;
        bia[jhi][0] = __ldg(bias + j);
        bia[jhi][1] = __ldg(bias + 1024 + j);
        bia[jhi][2] = __ldg(bias + 2048 + j);
        bia[jhi][3] = __ldg(bias + 3072 + j);
    }
    // c state in registers
    float cr[2][4][2];
#pragma unroll
    for (int a = 0; a < 2; a++)
#pragma unroll
        for (int b = 0; b < 4; b++) { cr[a][b][0] = 0.f; cr[a][b][1] = 0.f; }

    // prologue: x-ktiles 0..2 of t=0
    {
        const char* Bx = (const char*)g_xp + (size_t)(by * 16) * 16384;
        const char* Bh = (const char*)g_hp[0] + (size_t)(by * 16) * 16384;
        ISSUE_STAGE(0, 0, Bx, Bh); CP_COMMIT();
        ISSUE_STAGE(1, 1, Bx, Bh); CP_COMMIT();
        ISSUE_STAGE(2, 2, Bx, Bh); CP_COMMIT();
    }

    for (int t = 0; t < TSTEPS; t++) {
        const char* Bx  = (const char*)g_xp + (size_t)(t * 64 + by * 16) * 16384;
        const char* Bh  = (const char*)g_hp[t & 1] + (size_t)(by * 16) * 16384;
        const char* BxN = (const char*)g_xp + (size_t)((t + 1) * 64 + by * 16) * 16384;
        __half* hw = g_hp[(t & 1) ^ 1];

        float acc[4][4][4];
#pragma unroll
        for (int a = 0; a < 4; a++)
#pragma unroll
            for (int b = 0; b < 4; b++)
#pragma unroll
                for (int c = 0; c < 4; c++) acc[a][b][c] = 0.f;

        for (int kt = 0; kt < 32; kt++) {
            CP_WAIT2();
            __syncthreads();
            if (kt == 13) {
                // wait for this step's h (gen t) just before first h-tile issue
                if (t > 0 && tid == 0) {
                    const unsigned tgt = (unsigned)t * 32u;
                    while (*(volatile unsigned*)&g_sync4[by] < tgt) { }
                    __threadfence();
                }
                __syncthreads();
            }
            const int la = kt + 3;
            if (la < 32) {
                ISSUE_STAGE(la & 3, la, Bx, Bh);
            } else if (t + 1 < TSTEPS) {
                ISSUE_STAGE(la & 3, la - 32, BxN, Bh);   // next step's x-ktiles 0..2
            }
            CP_COMMIT();
            COMPUTE_STAGE(kt & 3);
        }

        // ---- fused LSTM epilogue (c in registers, fast transcendentals) ----
        float hnv[2][4][2];
#pragma unroll
        for (int jhi = 0; jhi < 2; jhi++) {
            const int j = j0 + jhi * 8 + grp;
            const int kt_  = j >> 6;
            const int k16_ = (j >> 4) & 3;
            const int reg_ = (j >> 3) & 1;
            const int tig_ = (j >> 1) & 3;
            const int u_   = j & 1;
            const int jbase = (kt_ * 4 + k16_) * 32;
#pragma unroll
            for (int nj = 0; nj < 4; nj++) {
                const int blk = by * 16 + wn * 4 + nj;
#pragma unroll
                for (int e = 0; e < 2; e++) {
                    const int grp_b = tig * 2 + e;
                    float zi = acc[2 * jhi    ][nj][e]     + bia[jhi][0];
                    float zf = acc[2 * jhi    ][nj][2 + e] + bia[jhi][1];
                    float zg = acc[2 * jhi + 1][nj][e]     + bia[jhi][2];
                    float zo = acc[2 * jhi + 1][nj][2 + e] + bia[jhi][3];

                    float si = sigm_f(zi);
                    float sf = sigm_f(zf);
                    float so = sigm_f(zo);
                    float tg = tanh_f(zg);

                    float cn = sf * cr[jhi][nj][e] + si * tg;
                    float hn = so * tanh_f(cn);
                    cr[jhi][nj][e] = cn;
                    hnv[jhi][nj][e] = hn;
                    hw[(size_t)blk * 8192 + (jbase + grp_b * 4 + tig_) * 4 + reg_ * 2 + u_] =
                        __float2half_rn(hn);
                }
            }
        }

        // publish h, arrive on group barrier, THEN write out (off critical path)
        __syncthreads();
        if (tid == 0) {
            __threadfence();
            atomicAdd(&g_sync4[by], 1u);
        }

#pragma unroll
        for (int jhi = 0; jhi < 2; jhi++) {
            const int j = j0 + jhi * 8 + grp;
#pragma unroll
            for (int nj = 0; nj < 4; nj++) {
                const int blk = by * 16 + wn * 4 + nj;
#pragma unroll
                for (int e = 0; e < 2; e++) {
                    const int b = blk * 8 + tig * 2 + e;
                    out[(size_t)b * (TSTEPS * HIDDEN) + (size_t)t * 1024 + j] = hnv[jhi][nj][e];
                }
            }
        }
    }
}

// ------------------------------ launch ----------------------------------------
extern "C" void kernel_launch(void* const* d_in, const int* in_sizes, int n_in,
                              void* d_out, int out_size)
{
    const float* x    = (const float*)d_in[0];  // [512, 103, 1024]
    const float* W    = (const float*)d_in[1];  // [1024, 4096]
    const float* R    = (const float*)d_in[2];  // [1024, 4096]
    const float* bias = (const float*)d_in[3];  // [4096]
    float* out = (float*)d_out;                 // [512, 100, 1024]

    cudaFuncSetAttribute(lstm_persist, cudaFuncAttributeMaxDynamicSharedMemorySize, SMEM_SZ);

    const int total = N1 + N2 + N3 + 4;
    prep_all<<<(total + 255) / 256, 256>>>(W, R, x);

    dim3 grid(32, 4);   // 128 CTAs, 1/SM, co-resident
    lstm_persist<<<grid, 256, SMEM_SZ>>>(bias, out);
}